// round 7
// baseline (speedup 1.0000x reference)
#include <cuda_runtime.h>
#include <cuda_fp16.h>
#include <cstdint>

#define BATCH     4
#define NHEAD     16
#define SEQ       2048
#define DHEAD     64
#define ROWSTRIDE 3072
#define NSTATE    1024
#define BM        64
#define BN        64
#define NTHREADS  128
#define KPAD      72
#define TILEH     (BN * KPAD)          // halves per array (4608)
#define BUFH      (4 * TILEH)          // halves per buffer (Kh,Kl,Vh,Vl)
#define BUFBYTES  (BUFH * 2)           // 36864
#define SMEM_TOTAL (2 * BUFBYTES)      // 73728

// scale * log2(e): softmax computed in log2 domain with ex2.approx
#define SCALE_LOG2E 0.18033688011112042f

__device__ __forceinline__ float ex2f(float x) {
    float y;
    asm("ex2.approx.f32 %0, %1;" : "=f"(y) : "f"(x));
    return y;
}

__device__ __forceinline__ uint32_t h2pack(float lo, float hi) {
    __half2 h = __floats2half2_rn(lo, hi);
    return *reinterpret_cast<uint32_t*>(&h);
}

__device__ __forceinline__ void split2(float fx, float fy, uint32_t& hi, uint32_t& lo) {
    __half hx = __float2half_rn(fx);
    __half hy = __float2half_rn(fy);
    __half2 hh = __halves2half2(hx, hy);
    hi = *reinterpret_cast<uint32_t*>(&hh);
    lo = h2pack(fx - __half2float(hx), fy - __half2float(hy));
}

__device__ __forceinline__ void mma16816(float* c, const uint32_t* a, uint32_t b0, uint32_t b1) {
    asm volatile(
        "mma.sync.aligned.m16n8k16.row.col.f32.f16.f16.f32 "
        "{%0,%1,%2,%3}, {%4,%5,%6,%7}, {%8,%9}, {%0,%1,%2,%3};"
        : "+f"(c[0]), "+f"(c[1]), "+f"(c[2]), "+f"(c[3])
        : "r"(a[0]), "r"(a[1]), "r"(a[2]), "r"(a[3]), "r"(b0), "r"(b1));
}

__device__ __forceinline__ void ldsm_x4(uint32_t& r0, uint32_t& r1, uint32_t& r2, uint32_t& r3,
                                        uint32_t addr) {
    asm volatile("ldmatrix.sync.aligned.m8n8.x4.shared.b16 {%0,%1,%2,%3}, [%4];"
                 : "=r"(r0), "=r"(r1), "=r"(r2), "=r"(r3) : "r"(addr));
}

__device__ __forceinline__ void ldsm_x4_t(uint32_t& r0, uint32_t& r1, uint32_t& r2, uint32_t& r3,
                                          uint32_t addr) {
    asm volatile("ldmatrix.sync.aligned.m8n8.x4.trans.shared.b16 {%0,%1,%2,%3}, [%4];"
                 : "=r"(r0), "=r"(r1), "=r"(r2), "=r"(r3) : "r"(addr));
}

// convert one thread's prefetched float4 pair set into hi/lo split smem tiles
__device__ __forceinline__ void convert_store(__half* sm, int bufh, int r, int c4,
                                              float4 kv, float4 vv) {
    __half* Kh = sm + bufh;
    __half* Kl = Kh + TILEH;
    __half* Vh = Kl + TILEH;
    __half* Vl = Vh + TILEH;
    const int idx = r * KPAD + c4;

    __half2 kh01 = __floats2half2_rn(kv.x, kv.y);
    __half2 kh23 = __floats2half2_rn(kv.z, kv.w);
    float2 kb01 = __half22float2(kh01);
    float2 kb23 = __half22float2(kh23);
    uint2 st;
    st.x = *reinterpret_cast<uint32_t*>(&kh01);
    st.y = *reinterpret_cast<uint32_t*>(&kh23);
    *reinterpret_cast<uint2*>(Kh + idx) = st;
    st.x = h2pack(kv.x - kb01.x, kv.y - kb01.y);
    st.y = h2pack(kv.z - kb23.x, kv.w - kb23.y);
    *reinterpret_cast<uint2*>(Kl + idx) = st;

    __half2 vh01 = __floats2half2_rn(vv.x, vv.y);
    __half2 vh23 = __floats2half2_rn(vv.z, vv.w);
    float2 vb01 = __half22float2(vh01);
    float2 vb23 = __half22float2(vh23);
    st.x = *reinterpret_cast<uint32_t*>(&vh01);
    st.y = *reinterpret_cast<uint32_t*>(&vh23);
    *reinterpret_cast<uint2*>(Vh + idx) = st;
    st.x = h2pack(vv.x - vb01.x, vv.y - vb01.y);
    st.y = h2pack(vv.z - vb23.x, vv.w - vb23.y);
    *reinterpret_cast<uint2*>(Vl + idx) = st;
}

__global__ __launch_bounds__(NTHREADS, 3)
void fa_kernel(const float* __restrict__ x, float* __restrict__ out) {
    extern __shared__ __half sm[];

    const int qtile = blockIdx.x;
    const int h     = blockIdx.y;
    const int b     = blockIdx.z;
    const int tid   = threadIdx.x;
    const int lane  = tid & 31;
    const int warp  = tid >> 5;
    const int g     = lane >> 2;
    const int qr    = lane & 3;

    const size_t base = (size_t)b * SEQ * ROWSTRIDE + (size_t)h * DHEAD;
    const int row0 = qtile * BM + warp * 16 + g;

    // ldmatrix per-lane selectors
    const int r8 = lane & 7;
    const int krow = (((lane >> 4) & 1) << 3) + r8;
    const int kcol = ((lane >> 3) & 1) << 3;
    const int vrow = (((lane >> 3) & 1) << 3) + r8;
    const int vcol = ((lane >> 4) & 1) << 3;

    const uint32_t smBase = (uint32_t)__cvta_generic_to_shared(sm);
    const uint32_t aKh = smBase + (uint32_t)((krow * KPAD + kcol) * 2);
    const uint32_t aKl = aKh + TILEH * 2;
    const uint32_t aVh = smBase + (uint32_t)((2 * TILEH + vrow * KPAD + vcol) * 2);
    const uint32_t aVl = aVh + TILEH * 2;

    // conversion loop indices for this thread
    int cr[8], cc[8];
#pragma unroll
    for (int i = 0; i < 8; i++) {
        const int fi = i * NTHREADS + tid;
        cr[i] = fi >> 4;
        cc[i] = (fi & 15) << 2;
    }

    // ---- Q fragments (hi/lo split), register resident ----
    uint32_t qh[4][4], ql[4][4];
#pragma unroll
    for (int ks = 0; ks < 4; ks++) {
        const int c = ks * 16 + qr * 2;
        const float* p0 = x + base + (size_t)row0 * ROWSTRIDE + c;
        const float* p1 = x + base + (size_t)(row0 + 8) * ROWSTRIDE + c;
        float2 f0 = *reinterpret_cast<const float2*>(p0);
        float2 f1 = *reinterpret_cast<const float2*>(p1);
        float2 f2 = *reinterpret_cast<const float2*>(p0 + 8);
        float2 f3 = *reinterpret_cast<const float2*>(p1 + 8);
        split2(f0.x, f0.y, qh[ks][0], ql[ks][0]);
        split2(f1.x, f1.y, qh[ks][1], ql[ks][1]);
        split2(f2.x, f2.y, qh[ks][2], ql[ks][2]);
        split2(f3.x, f3.y, qh[ks][3], ql[ks][3]);
    }

    float o[8][4];
#pragma unroll
    for (int nd = 0; nd < 8; nd++)
#pragma unroll
        for (int e = 0; e < 4; e++) o[nd][e] = 0.f;

    float m0 = -INFINITY, m1 = -INFINITY;
    float l0 = 0.f, l1 = 0.f;

    const int rl0 = warp * 16 + g;
    const int rl1 = rl0 + 8;
    const int tmin = qtile * BM + warp * 16;   // smallest query row in this warp's tile
    const int njt = qtile + 1;

    // ---- prologue: load + convert tile 0 into buffer 0 ----
    {
#pragma unroll
        for (int i = 0; i < 8; i++) {
            const float* rowp = x + base + (size_t)cr[i] * ROWSTRIDE;
            float4 kv = *reinterpret_cast<const float4*>(rowp + NSTATE + cc[i]);
            float4 vv = *reinterpret_cast<const float4*>(rowp + 2 * NSTATE + cc[i]);
            convert_store(sm, 0, cr[i], cc[i], kv, vv);
        }
    }
    __syncthreads();

    for (int j = 0; j < njt; j++) {
        const int buf = j & 1;
        const uint32_t bob = (uint32_t)buf * BUFBYTES;   // byte offset for ldsm
        const bool havenext = (j + 1 < njt);

        // ---- prefetch LDGs for tile j+1 (latency hidden by QK MMA phase) ----
        float4 pk[8], pv[8];
        if (havenext) {
            const int kb = (j + 1) * BN;
#pragma unroll
            for (int i = 0; i < 8; i++) {
                const float* rowp = x + base + (size_t)(kb + cr[i]) * ROWSTRIDE;
                pk[i] = *reinterpret_cast<const float4*>(rowp + NSTATE + cc[i]);
                pv[i] = *reinterpret_cast<const float4*>(rowp + 2 * NSTATE + cc[i]);
            }
        }

        // ---- S = Q K^T (3-term hi/lo split) on buffer buf ----
        float s[8][4];
#pragma unroll
        for (int nt = 0; nt < 8; nt++)
#pragma unroll
            for (int e = 0; e < 4; e++) s[nt][e] = 0.f;

#pragma unroll
        for (int ks = 0; ks < 4; ks++) {
#pragma unroll
            for (int ntp = 0; ntp < 4; ntp++) {
                const int nt = ntp * 2;
                const uint32_t off = bob + (uint32_t)((nt * 8 * KPAD + ks * 16) * 2);
                uint32_t bh0, bh1, bh2, bh3, bl0, bl1, bl2, bl3;
                ldsm_x4(bh0, bh1, bh2, bh3, aKh + off);
                ldsm_x4(bl0, bl1, bl2, bl3, aKl + off);
                mma16816(s[nt],     qh[ks], bh0, bh1);
                mma16816(s[nt],     ql[ks], bh0, bh1);
                mma16816(s[nt],     qh[ks], bl0, bl1);
                mma16816(s[nt + 1], qh[ks], bh2, bh3);
                mma16816(s[nt + 1], ql[ks], bh2, bh3);
                mma16816(s[nt + 1], qh[ks], bl2, bl3);
            }
        }

        // ---- convert prefetched tile j+1 into the other buffer ----
        if (havenext) {
            const int nb = (buf ^ 1) * BUFH;
#pragma unroll
            for (int i = 0; i < 8; i++)
                convert_store(sm, nb, cr[i], cc[i], pk[i], pv[i]);
        }

        // ---- scale (log2 domain), mask, online softmax ----
        const int kb = j * BN;
#pragma unroll
        for (int nt = 0; nt < 8; nt++)
#pragma unroll
            for (int e = 0; e < 4; e++) s[nt][e] *= SCALE_LOG2E;
        if (kb + BN - 1 > tmin) {
#pragma unroll
            for (int nt = 0; nt < 8; nt++) {
                const int kg = kb + nt * 8 + qr * 2;
                if (kg     > kb + rl0 - (kb - qtile * BM) + 0) {}  // (placeholder removed below)
            }
        }
        // masking (j == qtile is the only partially-masked tile since BN == BM block rows per warp span 16)
        if (kb + BN - 1 > tmin) {
#pragma unroll
            for (int nt = 0; nt < 8; nt++) {
                const int klocal = nt * 8 + qr * 2;   // key index within tile
                const int kg = kb + klocal;
                const int gq0 = qtile * BM + rl0;
                const int gq1 = qtile * BM + rl1;
                if (kg     > gq0) s[nt][0] = -1e30f;
                if (kg + 1 > gq0) s[nt][1] = -1e30f;
                if (kg     > gq1) s[nt][2] = -1e30f;
                if (kg + 1 > gq1) s[nt][3] = -1e30f;
            }
        }

        float mx0 = -INFINITY, mx1 = -INFINITY;
#pragma unroll
        for (int nt = 0; nt < 8; nt++) {
            mx0 = fmaxf(mx0, fmaxf(s[nt][0], s[nt][1]));
            mx1 = fmaxf(mx1, fmaxf(s[nt][2], s[nt][3]));
        }
        mx0 = fmaxf(mx0, __shfl_xor_sync(0xffffffffu, mx0, 1));
        mx0 = fmaxf(mx0, __shfl_xor_sync(0xffffffffu, mx0, 2));
        mx1 = fmaxf(mx1, __shfl_xor_sync(0xffffffffu, mx1, 1));
        mx1 = fmaxf(mx1, __shfl_xor_sync(0xffffffffu, mx1, 2));

        const float mn0 = fmaxf(m0, mx0);
        const float mn1 = fmaxf(m1, mx1);
        const float a0 = ex2f(m0 - mn0);
        const float a1 = ex2f(m1 - mn1);
        m0 = mn0; m1 = mn1;

        float sum0 = 0.f, sum1 = 0.f;
#pragma unroll
        for (int nt = 0; nt < 8; nt++) {
            s[nt][0] = ex2f(s[nt][0] - m0); sum0 += s[nt][0];
            s[nt][1] = ex2f(s[nt][1] - m0); sum0 += s[nt][1];
            s[nt][2] = ex2f(s[nt][2] - m1); sum1 += s[nt][2];
            s[nt][3] = ex2f(s[nt][3] - m1); sum1 += s[nt][3];
        }
        sum0 += __shfl_xor_sync(0xffffffffu, sum0, 1);
        sum0 += __shfl_xor_sync(0xffffffffu, sum0, 2);
        sum1 += __shfl_xor_sync(0xffffffffu, sum1, 1);
        sum1 += __shfl_xor_sync(0xffffffffu, sum1, 2);
        l0 = l0 * a0 + sum0;
        l1 = l1 * a1 + sum1;

#pragma unroll
        for (int nd = 0; nd < 8; nd++) {
            o[nd][0] *= a0; o[nd][1] *= a0;
            o[nd][2] *= a1; o[nd][3] *= a1;
        }

        // ---- O += P V (3-term split), V via ldmatrix.trans on buffer buf ----
#pragma unroll
        for (int ks2 = 0; ks2 < 4; ks2++) {
            const int n2 = ks2 * 2;
            uint32_t pah[4], pal[4];
            split2(s[n2][0],     s[n2][1],     pah[0], pal[0]);
            split2(s[n2][2],     s[n2][3],     pah[1], pal[1]);
            split2(s[n2 + 1][0], s[n2 + 1][1], pah[2], pal[2]);
            split2(s[n2 + 1][2], s[n2 + 1][3], pah[3], pal[3]);
#pragma unroll
            for (int ndp = 0; ndp < 4; ndp++) {
                const int nd = ndp * 2;
                const uint32_t off = bob + (uint32_t)((ks2 * 16 * KPAD + nd * 8) * 2);
                uint32_t bh0, bh1, bh2, bh3, bl0, bl1, bl2, bl3;
                ldsm_x4_t(bh0, bh1, bh2, bh3, aVh + off);
                ldsm_x4_t(bl0, bl1, bl2, bl3, aVl + off);
                mma16816(o[nd],     pah, bh0, bh1);
                mma16816(o[nd],     pal, bh0, bh1);
                mma16816(o[nd],     pah, bl0, bl1);
                mma16816(o[nd + 1], pah, bh2, bh3);
                mma16816(o[nd + 1], pal, bh2, bh3);
                mma16816(o[nd + 1], pah, bl2, bl3);
            }
        }
        __syncthreads();   // single barrier per iteration: buffer handoff
    }

    // ---- epilogue ----
    const float inv0 = 1.f / l0;
    const float inv1 = 1.f / l1;
    float* ob = out + (size_t)b * SEQ * NSTATE + (size_t)h * DHEAD;
#pragma unroll
    for (int nd = 0; nd < 8; nd++) {
        const int dcol = nd * 8 + qr * 2;
        float2 v0; v0.x = o[nd][0] * inv0; v0.y = o[nd][1] * inv0;
        float2 v1; v1.x = o[nd][2] * inv1; v1.y = o[nd][3] * inv1;
        *reinterpret_cast<float2*>(ob + (size_t)row0 * NSTATE + dcol) = v0;
        *reinterpret_cast<float2*>(ob + (size_t)(row0 + 8) * NSTATE + dcol) = v1;
    }
}

extern "C" void kernel_launch(void* const* d_in, const int* in_sizes, int n_in,
                              void* d_out, int out_size) {
    const float* x = (const float*)d_in[0];
    float* out = (float*)d_out;
    static bool attr_set = false;
    if (!attr_set) {
        cudaFuncSetAttribute(fa_kernel, cudaFuncAttributeMaxDynamicSharedMemorySize, SMEM_TOTAL);
        attr_set = true;
    }
    dim3 grid(SEQ / BM, NHEAD, BATCH);
    fa_kernel<<<grid, NTHREADS, SMEM_TOTAL>>>(x, out);
}

// round 12
// speedup vs baseline: 1.7011x; 1.7011x over previous
#include <cuda_runtime.h>
#include <cuda_fp16.h>
#include <cstdint>

#define BATCH     4
#define NHEAD     16
#define SEQ       2048
#define DHEAD     64
#define ROWSTRIDE 3072
#define NSTATE    1024
#define BM        64
#define BN        64
#define NTHREADS  128
#define KPAD      72

// scale * log2(e): softmax in log2 domain via ex2.approx
#define SCALE_LOG2E 0.18033688011112042f

__device__ __forceinline__ float ex2f(float x) {
    float y;
    asm("ex2.approx.f32 %0, %1;" : "=f"(y) : "f"(x));
    return y;
}

__device__ __forceinline__ uint32_t h2pack(float lo, float hi) {
    __half2 h = __floats2half2_rn(lo, hi);
    return *reinterpret_cast<uint32_t*>(&h);
}

__device__ __forceinline__ void split2(float fx, float fy, uint32_t& hi, uint32_t& lo) {
    __half hx = __float2half_rn(fx);
    __half hy = __float2half_rn(fy);
    __half2 hh = __halves2half2(hx, hy);
    hi = *reinterpret_cast<uint32_t*>(&hh);
    lo = h2pack(fx - __half2float(hx), fy - __half2float(hy));
}

__device__ __forceinline__ void mma16816(float* c, const uint32_t* a, uint32_t b0, uint32_t b1) {
    asm volatile(
        "mma.sync.aligned.m16n8k16.row.col.f32.f16.f16.f32 "
        "{%0,%1,%2,%3}, {%4,%5,%6,%7}, {%8,%9}, {%0,%1,%2,%3};"
        : "+f"(c[0]), "+f"(c[1]), "+f"(c[2]), "+f"(c[3])
        : "r"(a[0]), "r"(a[1]), "r"(a[2]), "r"(a[3]), "r"(b0), "r"(b1));
}

__device__ __forceinline__ void ldsm_x4(uint32_t& r0, uint32_t& r1, uint32_t& r2, uint32_t& r3,
                                        uint32_t addr) {
    asm volatile("ldmatrix.sync.aligned.m8n8.x4.shared.b16 {%0,%1,%2,%3}, [%4];"
                 : "=r"(r0), "=r"(r1), "=r"(r2), "=r"(r3) : "r"(addr));
}

__device__ __forceinline__ void ldsm_x4_t(uint32_t& r0, uint32_t& r1, uint32_t& r2, uint32_t& r3,
                                          uint32_t addr) {
    asm volatile("ldmatrix.sync.aligned.m8n8.x4.trans.shared.b16 {%0,%1,%2,%3}, [%4];"
                 : "=r"(r0), "=r"(r1), "=r"(r2), "=r"(r3) : "r"(addr));
}

__global__ __launch_bounds__(NTHREADS, 4)
void fa_kernel(const float* __restrict__ x, float* __restrict__ out) {
    // Only hi halves of K and V needed (2-term split corrects Q/P rounding only)
    __shared__ alignas(16) __half Kh[BN][KPAD];
    __shared__ alignas(16) __half Vh[BN][KPAD];

    const int qtile = blockIdx.x;
    const int h     = blockIdx.y;
    const int b     = blockIdx.z;
    const int tid   = threadIdx.x;
    const int lane  = tid & 31;
    const int warp  = tid >> 5;
    const int g     = lane >> 2;
    const int qr    = lane & 3;

    const size_t base = (size_t)b * SEQ * ROWSTRIDE + (size_t)h * DHEAD;
    const int row0 = qtile * BM + warp * 16 + g;

    // ldmatrix per-lane selectors
    const int r8 = lane & 7;
    const int krow = (((lane >> 4) & 1) << 3) + r8;
    const int kcol = ((lane >> 3) & 1) << 3;
    const int vrow = (((lane >> 3) & 1) << 3) + r8;
    const int vcol = ((lane >> 4) & 1) << 3;

    const uint32_t aKh = (uint32_t)__cvta_generic_to_shared(&Kh[krow][kcol]);
    const uint32_t aVh = (uint32_t)__cvta_generic_to_shared(&Vh[vrow][vcol]);

    // ---- Q fragments (hi/lo split), register resident ----
    uint32_t qh[4][4], ql[4][4];
#pragma unroll
    for (int ks = 0; ks < 4; ks++) {
        const int c = ks * 16 + qr * 2;
        const float* p0 = x + base + (size_t)row0 * ROWSTRIDE + c;
        const float* p1 = x + base + (size_t)(row0 + 8) * ROWSTRIDE + c;
        float2 f0 = *reinterpret_cast<const float2*>(p0);
        float2 f1 = *reinterpret_cast<const float2*>(p1);
        float2 f2 = *reinterpret_cast<const float2*>(p0 + 8);
        float2 f3 = *reinterpret_cast<const float2*>(p1 + 8);
        split2(f0.x, f0.y, qh[ks][0], ql[ks][0]);
        split2(f1.x, f1.y, qh[ks][1], ql[ks][1]);
        split2(f2.x, f2.y, qh[ks][2], ql[ks][2]);
        split2(f3.x, f3.y, qh[ks][3], ql[ks][3]);
    }

    float o[8][4];
#pragma unroll
    for (int nd = 0; nd < 8; nd++)
#pragma unroll
        for (int e = 0; e < 4; e++) o[nd][e] = 0.f;

    float m0 = -INFINITY, m1 = -INFINITY;
    float l0 = 0.f, l1 = 0.f;

    const int gq0 = qtile * BM + warp * 16 + g;   // global query row (== row0)
    const int gq1 = gq0 + 8;
    const int tmin = qtile * BM + warp * 16;
    const int njt = qtile + 1;

    for (int j = 0; j < njt; j++) {
        const int kb = j * BN;
        // ---- cooperative load + fp16 convert (hi only), STS.64 ----
#pragma unroll
        for (int i = 0; i < 8; i++) {
            const int fi = i * NTHREADS + tid;
            const int r  = fi >> 4;
            const int c4 = (fi & 15) << 2;
            const float* rowp = x + base + (size_t)(kb + r) * ROWSTRIDE;
            float4 kv = *reinterpret_cast<const float4*>(rowp + NSTATE + c4);
            float4 vv = *reinterpret_cast<const float4*>(rowp + 2 * NSTATE + c4);

            __half2 kh01 = __floats2half2_rn(kv.x, kv.y);
            __half2 kh23 = __floats2half2_rn(kv.z, kv.w);
            __half2 vh01 = __floats2half2_rn(vv.x, vv.y);
            __half2 vh23 = __floats2half2_rn(vv.z, vv.w);

            uint2 pk = {*reinterpret_cast<uint32_t*>(&kh01), *reinterpret_cast<uint32_t*>(&kh23)};
            uint2 pv = {*reinterpret_cast<uint32_t*>(&vh01), *reinterpret_cast<uint32_t*>(&vh23)};
            *reinterpret_cast<uint2*>(&Kh[r][c4]) = pk;
            *reinterpret_cast<uint2*>(&Vh[r][c4]) = pv;
        }
        __syncthreads();

        // ---- S = Q K^T (2-term: qh*Kh + ql*Kh) ----
        float s[8][4];
#pragma unroll
        for (int nt = 0; nt < 8; nt++)
#pragma unroll
            for (int e = 0; e < 4; e++) s[nt][e] = 0.f;

#pragma unroll
        for (int ks = 0; ks < 4; ks++) {
#pragma unroll
            for (int ntp = 0; ntp < 4; ntp++) {
                const int nt = ntp * 2;
                const uint32_t off = (uint32_t)((nt * 8 * KPAD + ks * 16) * 2);
                uint32_t bh0, bh1, bh2, bh3;
                ldsm_x4(bh0, bh1, bh2, bh3, aKh + off);
                mma16816(s[nt],     qh[ks], bh0, bh1);
                mma16816(s[nt],     ql[ks], bh0, bh1);
                mma16816(s[nt + 1], qh[ks], bh2, bh3);
                mma16816(s[nt + 1], ql[ks], bh2, bh3);
            }
        }

        // ---- scale (log2 domain), causal mask ----
#pragma unroll
        for (int nt = 0; nt < 8; nt++)
#pragma unroll
            for (int e = 0; e < 4; e++) s[nt][e] *= SCALE_LOG2E;
        if (kb + BN - 1 > tmin) {
#pragma unroll
            for (int nt = 0; nt < 8; nt++) {
                const int kg = kb + nt * 8 + qr * 2;
                if (kg     > gq0) s[nt][0] = -1e30f;
                if (kg + 1 > gq0) s[nt][1] = -1e30f;
                if (kg     > gq1) s[nt][2] = -1e30f;
                if (kg + 1 > gq1) s[nt][3] = -1e30f;
            }
        }

        // ---- online softmax (log2 domain) ----
        float mx0 = -INFINITY, mx1 = -INFINITY;
#pragma unroll
        for (int nt = 0; nt < 8; nt++) {
            mx0 = fmaxf(mx0, fmaxf(s[nt][0], s[nt][1]));
            mx1 = fmaxf(mx1, fmaxf(s[nt][2], s[nt][3]));
        }
        mx0 = fmaxf(mx0, __shfl_xor_sync(0xffffffffu, mx0, 1));
        mx0 = fmaxf(mx0, __shfl_xor_sync(0xffffffffu, mx0, 2));
        mx1 = fmaxf(mx1, __shfl_xor_sync(0xffffffffu, mx1, 1));
        mx1 = fmaxf(mx1, __shfl_xor_sync(0xffffffffu, mx1, 2));

        const float mn0 = fmaxf(m0, mx0);
        const float mn1 = fmaxf(m1, mx1);
        const float a0 = ex2f(m0 - mn0);
        const float a1 = ex2f(m1 - mn1);
        m0 = mn0; m1 = mn1;

        float sum0 = 0.f, sum1 = 0.f;
#pragma unroll
        for (int nt = 0; nt < 8; nt++) {
            s[nt][0] = ex2f(s[nt][0] - m0); sum0 += s[nt][0];
            s[nt][1] = ex2f(s[nt][1] - m0); sum0 += s[nt][1];
            s[nt][2] = ex2f(s[nt][2] - m1); sum1 += s[nt][2];
            s[nt][3] = ex2f(s[nt][3] - m1); sum1 += s[nt][3];
        }
        sum0 += __shfl_xor_sync(0xffffffffu, sum0, 1);
        sum0 += __shfl_xor_sync(0xffffffffu, sum0, 2);
        sum1 += __shfl_xor_sync(0xffffffffu, sum1, 1);
        sum1 += __shfl_xor_sync(0xffffffffu, sum1, 2);
        l0 = l0 * a0 + sum0;
        l1 = l1 * a1 + sum1;

#pragma unroll
        for (int nd = 0; nd < 8; nd++) {
            o[nd][0] *= a0; o[nd][1] *= a0;
            o[nd][2] *= a1; o[nd][3] *= a1;
        }

        // ---- O += P V (2-term: ph*Vh + pl*Vh), V via ldmatrix.trans ----
#pragma unroll
        for (int ks2 = 0; ks2 < 4; ks2++) {
            const int n2 = ks2 * 2;
            uint32_t pah[4], pal[4];
            split2(s[n2][0],     s[n2][1],     pah[0], pal[0]);
            split2(s[n2][2],     s[n2][3],     pah[1], pal[1]);
            split2(s[n2 + 1][0], s[n2 + 1][1], pah[2], pal[2]);
            split2(s[n2 + 1][2], s[n2 + 1][3], pah[3], pal[3]);
#pragma unroll
            for (int ndp = 0; ndp < 4; ndp++) {
                const int nd = ndp * 2;
                const uint32_t off = (uint32_t)((ks2 * 16 * KPAD + nd * 8) * 2);
                uint32_t bh0, bh1, bh2, bh3;
                ldsm_x4_t(bh0, bh1, bh2, bh3, aVh + off);
                mma16816(o[nd],     pah, bh0, bh1);
                mma16816(o[nd],     pal, bh0, bh1);
                mma16816(o[nd + 1], pah, bh2, bh3);
                mma16816(o[nd + 1], pal, bh2, bh3);
            }
        }
        __syncthreads();
    }

    // ---- epilogue ----
    const float inv0 = 1.f / l0;
    const float inv1 = 1.f / l1;
    float* ob = out + (size_t)b * SEQ * NSTATE + (size_t)h * DHEAD;
#pragma unroll
    for (int nd = 0; nd < 8; nd++) {
        const int dcol = nd * 8 + qr * 2;
        float2 v0; v0.x = o[nd][0] * inv0; v0.y = o[nd][1] * inv0;
        float2 v1; v1.x = o[nd][2] * inv1; v1.y = o[nd][3] * inv1;
        *reinterpret_cast<float2*>(ob + (size_t)row0 * NSTATE + dcol) = v0;
        *reinterpret_cast<float2*>(ob + (size_t)(row0 + 8) * NSTATE + dcol) = v1;
    }
}

extern "C" void kernel_launch(void* const* d_in, const int* in_sizes, int n_in,
                              void* d_out, int out_size) {
    const float* x = (const float*)d_in[0];
    float* out = (float*)d_out;
    dim3 grid(SEQ / BM, NHEAD, BATCH);
    fa_kernel<<<grid, NTHREADS>>>(x, out);
}

// round 14
// speedup vs baseline: 1.9810x; 1.1645x over previous
#include <cuda_runtime.h>
#include <cuda_fp16.h>
#include <cstdint>

#define BATCH     4
#define NHEAD     16
#define SEQ       2048
#define DHEAD     64
#define ROWSTRIDE 3072
#define NSTATE    1024
#define BM        64
#define BN        64
#define NTHREADS  128
#define KPAD      72

// scale * log2(e), folded into Q before the hi/lo split
#define SCALE_LOG2E 0.18033688011112042f

// fp16 K/V scratch: [B][H][S][D], D contiguous
__device__ __half KC[BATCH * NHEAD * SEQ * DHEAD];
__device__ __half VC[BATCH * NHEAD * SEQ * DHEAD];

__device__ __forceinline__ float ex2f(float x) {
    float y;
    asm("ex2.approx.f32 %0, %1;" : "=f"(y) : "f"(x));
    return y;
}

__device__ __forceinline__ uint32_t h2bits(__half2 h) { return *reinterpret_cast<uint32_t*>(&h); }

__device__ __forceinline__ void split2(float fx, float fy, uint32_t& hi, uint32_t& lo) {
    __half hx = __float2half_rn(fx);
    __half hy = __float2half_rn(fy);
    __half2 hh = __halves2half2(hx, hy);
    hi = *reinterpret_cast<uint32_t*>(&hh);
    __half2 ll = __floats2half2_rn(fx - __half2float(hx), fy - __half2float(hy));
    lo = *reinterpret_cast<uint32_t*>(&ll);
}

__device__ __forceinline__ void mma16816(float* c, const uint32_t* a, uint32_t b0, uint32_t b1) {
    asm volatile(
        "mma.sync.aligned.m16n8k16.row.col.f32.f16.f16.f32 "
        "{%0,%1,%2,%3}, {%4,%5,%6,%7}, {%8,%9}, {%0,%1,%2,%3};"
        : "+f"(c[0]), "+f"(c[1]), "+f"(c[2]), "+f"(c[3])
        : "r"(a[0]), "r"(a[1]), "r"(a[2]), "r"(a[3]), "r"(b0), "r"(b1));
}

__device__ __forceinline__ void ldsm_x4(uint32_t& r0, uint32_t& r1, uint32_t& r2, uint32_t& r3,
                                        uint32_t addr) {
    asm volatile("ldmatrix.sync.aligned.m8n8.x4.shared.b16 {%0,%1,%2,%3}, [%4];"
                 : "=r"(r0), "=r"(r1), "=r"(r2), "=r"(r3) : "r"(addr));
}

__device__ __forceinline__ void ldsm_x4_t(uint32_t& r0, uint32_t& r1, uint32_t& r2, uint32_t& r3,
                                          uint32_t addr) {
    asm volatile("ldmatrix.sync.aligned.m8n8.x4.trans.shared.b16 {%0,%1,%2,%3}, [%4];"
                 : "=r"(r0), "=r"(r1), "=r"(r2), "=r"(r3) : "r"(addr));
}

#define CP_ASYNC16(dst, src) \
    asm volatile("cp.async.ca.shared.global [%0], [%1], 16;" :: "r"(dst), "l"(src))
#define CP_COMMIT() asm volatile("cp.async.commit_group;" ::: "memory")
#define CP_WAIT(n)  asm volatile("cp.async.wait_group %0;" :: "n"(n) : "memory")

// ---------------- pre-conversion kernel: x(K,V fp32) -> KC/VC fp16 ----------------
// One block per (b,s) row. K row = 1024 floats = 512 float2 pairs; 256 threads x 2 iters.
__global__ __launch_bounds__(256)
void conv_kernel(const float* __restrict__ x) {
    const int bs = blockIdx.x;           // b*SEQ + s
    const int b  = bs >> 11;
    const int s  = bs & 2047;
    const float* px = x + (size_t)bs * ROWSTRIDE;
    uint32_t* kc = reinterpret_cast<uint32_t*>(KC);
    uint32_t* vc = reinterpret_cast<uint32_t*>(VC);
#pragma unroll
    for (int it = 0; it < 2; it++) {
        const int p  = it * 256 + threadIdx.x;   // pair index [0,512)
        const int hh = p >> 5;                   // head (32 pairs = 64 floats per head)
        const int dp = p & 31;
        float2 kf = *reinterpret_cast<const float2*>(px + NSTATE + hh * 64 + dp * 2);
        float2 vf = *reinterpret_cast<const float2*>(px + 2 * NSTATE + hh * 64 + dp * 2);
        const size_t o = ((size_t)(b * NHEAD + hh) * SEQ + s) * 32 + dp;
        kc[o] = h2bits(__floats2half2_rn(kf.x, kf.y));
        vc[o] = h2bits(__floats2half2_rn(vf.x, vf.y));
    }
}

// ---------------- attention kernel ----------------
__global__ __launch_bounds__(NTHREADS, 4)
void fa_kernel(const float* __restrict__ x, float* __restrict__ out) {
    __shared__ alignas(16) __half KB[2][BN][KPAD];
    __shared__ alignas(16) __half VB[2][BN][KPAD];

    const int qtile = blockIdx.x;
    const int h     = blockIdx.y;
    const int b     = blockIdx.z;
    const int tid   = threadIdx.x;
    const int lane  = tid & 31;
    const int warp  = tid >> 5;
    const int g     = lane >> 2;
    const int qr    = lane & 3;

    const size_t base  = (size_t)b * SEQ * ROWSTRIDE + (size_t)h * DHEAD;
    const size_t kvrow = (size_t)(b * NHEAD + h) * SEQ;
    const int row0 = qtile * BM + warp * 16 + g;

    // ldmatrix per-lane selectors
    const int r8 = lane & 7;
    const int krow = (((lane >> 4) & 1) << 3) + r8;
    const int kcol = ((lane >> 3) & 1) << 3;
    const int vrow = (((lane >> 3) & 1) << 3) + r8;
    const int vcol = ((lane >> 4) & 1) << 3;

    const uint32_t aK0 = (uint32_t)__cvta_generic_to_shared(&KB[0][krow][kcol]);
    const uint32_t aV0 = (uint32_t)__cvta_generic_to_shared(&VB[0][vrow][vcol]);
    const uint32_t bufStride = (uint32_t)(BN * KPAD * 2);

    // cp.async chunk indices: 512 chunks of 16B per array, 4 per thread
    int lr[4], lc[4];
#pragma unroll
    for (int i = 0; i < 4; i++) {
        const int fi = i * NTHREADS + tid;
        lr[i] = fi >> 3;
        lc[i] = (fi & 7) << 3;
    }

    // ---- Q fragments (pre-scaled hi/lo split), register resident ----
    uint32_t qh[4][4], ql[4][4];
#pragma unroll
    for (int ks = 0; ks < 4; ks++) {
        const int c = ks * 16 + qr * 2;
        const float* p0 = x + base + (size_t)row0 * ROWSTRIDE + c;
        const float* p1 = x + base + (size_t)(row0 + 8) * ROWSTRIDE + c;
        float2 f0 = *reinterpret_cast<const float2*>(p0);
        float2 f1 = *reinterpret_cast<const float2*>(p1);
        float2 f2 = *reinterpret_cast<const float2*>(p0 + 8);
        float2 f3 = *reinterpret_cast<const float2*>(p1 + 8);
        split2(f0.x * SCALE_LOG2E, f0.y * SCALE_LOG2E, qh[ks][0], ql[ks][0]);
        split2(f1.x * SCALE_LOG2E, f1.y * SCALE_LOG2E, qh[ks][1], ql[ks][1]);
        split2(f2.x * SCALE_LOG2E, f2.y * SCALE_LOG2E, qh[ks][2], ql[ks][2]);
        split2(f3.x * SCALE_LOG2E, f3.y * SCALE_LOG2E, qh[ks][3], ql[ks][3]);
    }

    float o[8][4];
#pragma unroll
    for (int nd = 0; nd < 8; nd++)
#pragma unroll
        for (int e = 0; e < 4; e++) o[nd][e] = 0.f;

    float m0 = -INFINITY, m1 = -INFINITY;
    float l0 = 0.f, l1 = 0.f;

    const int gq0 = row0;
    const int gq1 = row0 + 8;
    const int tmin = qtile * BM + warp * 16;
    const int njt = qtile + 1;

    // ---- prologue: async-load tile 0 into buffer 0 ----
#pragma unroll
    for (int i = 0; i < 4; i++) {
        const __half* ksrc = KC + (kvrow + lr[i]) * DHEAD + lc[i];
        const __half* vsrc = VC + (kvrow + lr[i]) * DHEAD + lc[i];
        CP_ASYNC16((uint32_t)__cvta_generic_to_shared(&KB[0][lr[i]][lc[i]]), ksrc);
        CP_ASYNC16((uint32_t)__cvta_generic_to_shared(&VB[0][lr[i]][lc[i]]), vsrc);
    }
    CP_COMMIT();

    for (int j = 0; j < njt; j++) {
        const int buf = j & 1;
        const uint32_t bob = (uint32_t)buf * bufStride;

        if (j + 1 < njt) {
            const int kb = (j + 1) * BN;
            const int nb = buf ^ 1;
#pragma unroll
            for (int i = 0; i < 4; i++) {
                const __half* ksrc = KC + (kvrow + kb + lr[i]) * DHEAD + lc[i];
                const __half* vsrc = VC + (kvrow + kb + lr[i]) * DHEAD + lc[i];
                CP_ASYNC16((uint32_t)__cvta_generic_to_shared(&KB[nb][lr[i]][lc[i]]), ksrc);
                CP_ASYNC16((uint32_t)__cvta_generic_to_shared(&VB[nb][lr[i]][lc[i]]), vsrc);
            }
            CP_COMMIT();
            CP_WAIT(1);
        } else {
            CP_WAIT(0);
        }
        __syncthreads();

        // ---- S = Q K^T (2-term: qh*K + ql*K) ----
        float s[8][4];
#pragma unroll
        for (int nt = 0; nt < 8; nt++)
#pragma unroll
            for (int e = 0; e < 4; e++) s[nt][e] = 0.f;

#pragma unroll
        for (int ks = 0; ks < 4; ks++) {
#pragma unroll
            for (int ntp = 0; ntp < 4; ntp++) {
                const int nt = ntp * 2;
                const uint32_t off = bob + (uint32_t)((nt * 8 * KPAD + ks * 16) * 2);
                uint32_t bh0, bh1, bh2, bh3;
                ldsm_x4(bh0, bh1, bh2, bh3, aK0 + off);
                mma16816(s[nt],     qh[ks], bh0, bh1);
                mma16816(s[nt],     ql[ks], bh0, bh1);
                mma16816(s[nt + 1], qh[ks], bh2, bh3);
                mma16816(s[nt + 1], ql[ks], bh2, bh3);
            }
        }

        // ---- causal mask (logits already in log2 domain) ----
        const int kb = j * BN;
        if (kb + BN - 1 > tmin) {
#pragma unroll
            for (int nt = 0; nt < 8; nt++) {
                const int kg = kb + nt * 8 + qr * 2;
                if (kg     > gq0) s[nt][0] = -1e30f;
                if (kg + 1 > gq0) s[nt][1] = -1e30f;
                if (kg     > gq1) s[nt][2] = -1e30f;
                if (kg + 1 > gq1) s[nt][3] = -1e30f;
            }
        }

        // ---- online softmax (log2 domain) ----
        float mx0 = -INFINITY, mx1 = -INFINITY;
#pragma unroll
        for (int nt = 0; nt < 8; nt++) {
            mx0 = fmaxf(mx0, fmaxf(s[nt][0], s[nt][1]));
            mx1 = fmaxf(mx1, fmaxf(s[nt][2], s[nt][3]));
        }
        mx0 = fmaxf(mx0, __shfl_xor_sync(0xffffffffu, mx0, 1));
        mx0 = fmaxf(mx0, __shfl_xor_sync(0xffffffffu, mx0, 2));
        mx1 = fmaxf(mx1, __shfl_xor_sync(0xffffffffu, mx1, 1));
        mx1 = fmaxf(mx1, __shfl_xor_sync(0xffffffffu, mx1, 2));

        const float mn0 = fmaxf(m0, mx0);
        const float mn1 = fmaxf(m1, mx1);
        const float a0 = ex2f(m0 - mn0);
        const float a1 = ex2f(m1 - mn1);
        m0 = mn0; m1 = mn1;

        float sum0 = 0.f, sum1 = 0.f;
#pragma unroll
        for (int nt = 0; nt < 8; nt++) {
            s[nt][0] = ex2f(s[nt][0] - m0); sum0 += s[nt][0];
            s[nt][1] = ex2f(s[nt][1] - m0); sum0 += s[nt][1];
            s[nt][2] = ex2f(s[nt][2] - m1); sum1 += s[nt][2];
            s[nt][3] = ex2f(s[nt][3] - m1); sum1 += s[nt][3];
        }
        sum0 += __shfl_xor_sync(0xffffffffu, sum0, 1);
        sum0 += __shfl_xor_sync(0xffffffffu, sum0, 2);
        sum1 += __shfl_xor_sync(0xffffffffu, sum1, 1);
        sum1 += __shfl_xor_sync(0xffffffffu, sum1, 2);
        l0 = l0 * a0 + sum0;
        l1 = l1 * a1 + sum1;

#pragma unroll
        for (int nd = 0; nd < 8; nd++) {
            o[nd][0] *= a0; o[nd][1] *= a0;
            o[nd][2] *= a1; o[nd][3] *= a1;
        }

        // ---- O += P V (2-term), V via ldmatrix.trans ----
#pragma unroll
        for (int ks2 = 0; ks2 < 4; ks2++) {
            const int n2 = ks2 * 2;
            uint32_t pah[4], pal[4];
            split2(s[n2][0],     s[n2][1],     pah[0], pal[0]);
            split2(s[n2][2],     s[n2][3],     pah[1], pal[1]);
            split2(s[n2 + 1][0], s[n2 + 1][1], pah[2], pal[2]);
            split2(s[n2 + 1][2], s[n2 + 1][3], pah[3], pal[3]);
#pragma unroll
            for (int ndp = 0; ndp < 4; ndp++) {
                const int nd = ndp * 2;
                const uint32_t off = bob + (uint32_t)((ks2 * 16 * KPAD + nd * 8) * 2);
                uint32_t bh0, bh1, bh2, bh3;
                ldsm_x4_t(bh0, bh1, bh2, bh3, aV0 + off);
                mma16816(o[nd],     pah, bh0, bh1);
                mma16816(o[nd],     pal, bh0, bh1);
                mma16816(o[nd + 1], pah, bh2, bh3);
                mma16816(o[nd + 1], pal, bh2, bh3);
            }
        }
        __syncthreads();
    }

    // ---- epilogue ----
    const float inv0 = 1.f / l0;
    const float inv1 = 1.f / l1;
    float* ob = out + (size_t)b * SEQ * NSTATE + (size_t)h * DHEAD;
#pragma unroll
    for (int nd = 0; nd < 8; nd++) {
        const int dcol = nd * 8 + qr * 2;
        float2 v0; v0.x = o[nd][0] * inv0; v0.y = o[nd][1] * inv0;
        float2 v1; v1.x = o[nd][2] * inv1; v1.y = o[nd][3] * inv1;
        *reinterpret_cast<float2*>(ob + (size_t)row0 * NSTATE + dcol) = v0;
        *reinterpret_cast<float2*>(ob + (size_t)(row0 + 8) * NSTATE + dcol) = v1;
    }
}

extern "C" void kernel_launch(void* const* d_in, const int* in_sizes, int n_in,
                              void* d_out, int out_size) {
    const float* x = (const float*)d_in[0];
    float* out = (float*)d_out;
    conv_kernel<<<BATCH * SEQ, 256>>>(x);
    dim3 grid(SEQ / BM, NHEAD, BATCH);
    fa_kernel<<<grid, NTHREADS>>>(x, out);
}

// round 15
// speedup vs baseline: 2.9515x; 1.4899x over previous
#include <cuda_runtime.h>
#include <cuda_fp16.h>
#include <cstdint>

#define BATCH     4
#define NHEAD     16
#define SEQ       2048
#define DHEAD     64
#define ROWSTRIDE 3072
#define NSTATE    1024
#define BM        64
#define BN        64
#define NTHREADS  128
#define KPAD      72

// scale * log2(e), folded into Q
#define SCALE_LOG2E 0.18033688011112042f

// fp16 K/V scratch: [B][H][S][D], D contiguous
__device__ __half KC[BATCH * NHEAD * SEQ * DHEAD];
__device__ __half VC[BATCH * NHEAD * SEQ * DHEAD];

__device__ __forceinline__ float ex2f(float x) {
    float y;
    asm("ex2.approx.f32 %0, %1;" : "=f"(y) : "f"(x));
    return y;
}

__device__ __forceinline__ uint32_t h2bits(__half2 h) { return *reinterpret_cast<uint32_t*>(&h); }

__device__ __forceinline__ void mma16816(float* c, const uint32_t* a, uint32_t b0, uint32_t b1) {
    asm volatile(
        "mma.sync.aligned.m16n8k16.row.col.f32.f16.f16.f32 "
        "{%0,%1,%2,%3}, {%4,%5,%6,%7}, {%8,%9}, {%0,%1,%2,%3};"
        : "+f"(c[0]), "+f"(c[1]), "+f"(c[2]), "+f"(c[3])
        : "r"(a[0]), "r"(a[1]), "r"(a[2]), "r"(a[3]), "r"(b0), "r"(b1));
}

__device__ __forceinline__ void ldsm_x4(uint32_t& r0, uint32_t& r1, uint32_t& r2, uint32_t& r3,
                                        uint32_t addr) {
    asm volatile("ldmatrix.sync.aligned.m8n8.x4.shared.b16 {%0,%1,%2,%3}, [%4];"
                 : "=r"(r0), "=r"(r1), "=r"(r2), "=r"(r3) : "r"(addr));
}

__device__ __forceinline__ void ldsm_x4_t(uint32_t& r0, uint32_t& r1, uint32_t& r2, uint32_t& r3,
                                          uint32_t addr) {
    asm volatile("ldmatrix.sync.aligned.m8n8.x4.trans.shared.b16 {%0,%1,%2,%3}, [%4];"
                 : "=r"(r0), "=r"(r1), "=r"(r2), "=r"(r3) : "r"(addr));
}

#define CP_ASYNC16(dst, src) \
    asm volatile("cp.async.ca.shared.global [%0], [%1], 16;" :: "r"(dst), "l"(src))
#define CP_COMMIT() asm volatile("cp.async.commit_group;" ::: "memory")
#define CP_WAIT(n)  asm volatile("cp.async.wait_group %0;" :: "n"(n) : "memory")

// ---------------- pre-conversion: x(K,V fp32) -> KC/VC fp16 ----------------
__global__ __launch_bounds__(256)
void conv_kernel(const float* __restrict__ x) {
    const int bs = blockIdx.x;
    const int b  = bs >> 11;
    const int s  = bs & 2047;
    const float* px = x + (size_t)bs * ROWSTRIDE;
    uint32_t* kc = reinterpret_cast<uint32_t*>(KC);
    uint32_t* vc = reinterpret_cast<uint32_t*>(VC);
#pragma unroll
    for (int it = 0; it < 2; it++) {
        const int p  = it * 256 + threadIdx.x;   // pair index [0,512)
        const int hh = p >> 5;
        const int dp = p & 31;
        float2 kf = *reinterpret_cast<const float2*>(px + NSTATE + hh * 64 + dp * 2);
        float2 vf = *reinterpret_cast<const float2*>(px + 2 * NSTATE + hh * 64 + dp * 2);
        const size_t o = ((size_t)(b * NHEAD + hh) * SEQ + s) * 32 + dp;
        kc[o] = h2bits(__floats2half2_rn(kf.x, kf.y));
        vc[o] = h2bits(__floats2half2_rn(vf.x, vf.y));
    }
}

// ---------------- attention kernel ----------------
__global__ __launch_bounds__(NTHREADS, 4)
void fa_kernel(const float* __restrict__ x, float* __restrict__ out) {
    __shared__ alignas(16) __half KB[2][BN][KPAD];
    __shared__ alignas(16) __half VB[2][BN][KPAD];

    const int qtile = blockIdx.x;
    const int h     = blockIdx.y;
    const int b     = blockIdx.z;
    const int tid   = threadIdx.x;
    const int lane  = tid & 31;
    const int warp  = tid >> 5;
    const int g     = lane >> 2;
    const int qr    = lane & 3;

    const size_t base  = (size_t)b * SEQ * ROWSTRIDE + (size_t)h * DHEAD;
    const size_t kvrow = (size_t)(b * NHEAD + h) * SEQ;
    const int row0 = qtile * BM + warp * 16 + g;

    const int r8 = lane & 7;
    const int krow = (((lane >> 4) & 1) << 3) + r8;
    const int kcol = ((lane >> 3) & 1) << 3;
    const int vrow = (((lane >> 3) & 1) << 3) + r8;
    const int vcol = ((lane >> 4) & 1) << 3;

    const uint32_t aK0 = (uint32_t)__cvta_generic_to_shared(&KB[0][krow][kcol]);
    const uint32_t aV0 = (uint32_t)__cvta_generic_to_shared(&VB[0][vrow][vcol]);
    const uint32_t bufStride = (uint32_t)(BN * KPAD * 2);

    int lr[4], lc[4];
#pragma unroll
    for (int i = 0; i < 4; i++) {
        const int fi = i * NTHREADS + tid;
        lr[i] = fi >> 3;
        lc[i] = (fi & 7) << 3;
    }

    // ---- Q fragments (pre-scaled, single fp16 term) ----
    uint32_t qh[4][4];
#pragma unroll
    for (int ks = 0; ks < 4; ks++) {
        const int c = ks * 16 + qr * 2;
        const float* p0 = x + base + (size_t)row0 * ROWSTRIDE + c;
        const float* p1 = x + base + (size_t)(row0 + 8) * ROWSTRIDE + c;
        float2 f0 = *reinterpret_cast<const float2*>(p0);
        float2 f1 = *reinterpret_cast<const float2*>(p1);
        float2 f2 = *reinterpret_cast<const float2*>(p0 + 8);
        float2 f3 = *reinterpret_cast<const float2*>(p1 + 8);
        qh[ks][0] = h2bits(__floats2half2_rn(f0.x * SCALE_LOG2E, f0.y * SCALE_LOG2E));
        qh[ks][1] = h2bits(__floats2half2_rn(f1.x * SCALE_LOG2E, f1.y * SCALE_LOG2E));
        qh[ks][2] = h2bits(__floats2half2_rn(f2.x * SCALE_LOG2E, f2.y * SCALE_LOG2E));
        qh[ks][3] = h2bits(__floats2half2_rn(f3.x * SCALE_LOG2E, f3.y * SCALE_LOG2E));
    }

    float o[8][4];
#pragma unroll
    for (int nd = 0; nd < 8; nd++)
#pragma unroll
        for (int e = 0; e < 4; e++) o[nd][e] = 0.f;

    float m0 = -INFINITY, m1 = -INFINITY;
    float l0 = 0.f, l1 = 0.f;

    const int gq0 = row0;
    const int gq1 = row0 + 8;
    const int tmin = qtile * BM + warp * 16;
    const int njt = qtile + 1;

    // ---- prologue: async-load tile 0 ----
#pragma unroll
    for (int i = 0; i < 4; i++) {
        const __half* ksrc = KC + (kvrow + lr[i]) * DHEAD + lc[i];
        const __half* vsrc = VC + (kvrow + lr[i]) * DHEAD + lc[i];
        CP_ASYNC16((uint32_t)__cvta_generic_to_shared(&KB[0][lr[i]][lc[i]]), ksrc);
        CP_ASYNC16((uint32_t)__cvta_generic_to_shared(&VB[0][lr[i]][lc[i]]), vsrc);
    }
    CP_COMMIT();

    for (int j = 0; j < njt; j++) {
        const int buf = j & 1;
        const uint32_t bob = (uint32_t)buf * bufStride;

        if (j + 1 < njt) {
            const int kb = (j + 1) * BN;
            const int nb = buf ^ 1;
#pragma unroll
            for (int i = 0; i < 4; i++) {
                const __half* ksrc = KC + (kvrow + kb + lr[i]) * DHEAD + lc[i];
                const __half* vsrc = VC + (kvrow + kb + lr[i]) * DHEAD + lc[i];
                CP_ASYNC16((uint32_t)__cvta_generic_to_shared(&KB[nb][lr[i]][lc[i]]), ksrc);
                CP_ASYNC16((uint32_t)__cvta_generic_to_shared(&VB[nb][lr[i]][lc[i]]), vsrc);
            }
            CP_COMMIT();
            CP_WAIT(1);
        } else {
            CP_WAIT(0);
        }
        __syncthreads();

        // ---- S = Q K^T (single term) ----
        float s[8][4];
#pragma unroll
        for (int nt = 0; nt < 8; nt++)
#pragma unroll
            for (int e = 0; e < 4; e++) s[nt][e] = 0.f;

#pragma unroll
        for (int ks = 0; ks < 4; ks++) {
#pragma unroll
            for (int ntp = 0; ntp < 4; ntp++) {
                const int nt = ntp * 2;
                const uint32_t off = bob + (uint32_t)((nt * 8 * KPAD + ks * 16) * 2);
                uint32_t bh0, bh1, bh2, bh3;
                ldsm_x4(bh0, bh1, bh2, bh3, aK0 + off);
                mma16816(s[nt],     qh[ks], bh0, bh1);
                mma16816(s[nt + 1], qh[ks], bh2, bh3);
            }
        }

        // ---- causal mask (logits in log2 domain) ----
        const int kb = j * BN;
        if (kb + BN - 1 > tmin) {
#pragma unroll
            for (int nt = 0; nt < 8; nt++) {
                const int kg = kb + nt * 8 + qr * 2;
                if (kg     > gq0) s[nt][0] = -1e30f;
                if (kg + 1 > gq0) s[nt][1] = -1e30f;
                if (kg     > gq1) s[nt][2] = -1e30f;
                if (kg + 1 > gq1) s[nt][3] = -1e30f;
            }
        }

        // ---- online softmax (log2 domain) ----
        float mx0 = -INFINITY, mx1 = -INFINITY;
#pragma unroll
        for (int nt = 0; nt < 8; nt++) {
            mx0 = fmaxf(mx0, fmaxf(s[nt][0], s[nt][1]));
            mx1 = fmaxf(mx1, fmaxf(s[nt][2], s[nt][3]));
        }
        mx0 = fmaxf(mx0, __shfl_xor_sync(0xffffffffu, mx0, 1));
        mx0 = fmaxf(mx0, __shfl_xor_sync(0xffffffffu, mx0, 2));
        mx1 = fmaxf(mx1, __shfl_xor_sync(0xffffffffu, mx1, 1));
        mx1 = fmaxf(mx1, __shfl_xor_sync(0xffffffffu, mx1, 2));

        const float mn0 = fmaxf(m0, mx0);
        const float mn1 = fmaxf(m1, mx1);
        const float a0 = ex2f(m0 - mn0);
        const float a1 = ex2f(m1 - mn1);
        m0 = mn0; m1 = mn1;

        float sum0 = 0.f, sum1 = 0.f;
#pragma unroll
        for (int nt = 0; nt < 8; nt++) {
            s[nt][0] = ex2f(s[nt][0] - m0); sum0 += s[nt][0];
            s[nt][1] = ex2f(s[nt][1] - m0); sum0 += s[nt][1];
            s[nt][2] = ex2f(s[nt][2] - m1); sum1 += s[nt][2];
            s[nt][3] = ex2f(s[nt][3] - m1); sum1 += s[nt][3];
        }
        sum0 += __shfl_xor_sync(0xffffffffu, sum0, 1);
        sum0 += __shfl_xor_sync(0xffffffffu, sum0, 2);
        sum1 += __shfl_xor_sync(0xffffffffu, sum1, 1);
        sum1 += __shfl_xor_sync(0xffffffffu, sum1, 2);
        l0 = l0 * a0 + sum0;
        l1 = l1 * a1 + sum1;

#pragma unroll
        for (int nd = 0; nd < 8; nd++) {
            o[nd][0] *= a0; o[nd][1] *= a0;
            o[nd][2] *= a1; o[nd][3] *= a1;
        }

        // ---- O += P V (single term), V via ldmatrix.trans ----
#pragma unroll
        for (int ks2 = 0; ks2 < 4; ks2++) {
            const int n2 = ks2 * 2;
            uint32_t pah[4];
            pah[0] = h2bits(__floats2half2_rn(s[n2][0],     s[n2][1]));
            pah[1] = h2bits(__floats2half2_rn(s[n2][2],     s[n2][3]));
            pah[2] = h2bits(__floats2half2_rn(s[n2 + 1][0], s[n2 + 1][1]));
            pah[3] = h2bits(__floats2half2_rn(s[n2 + 1][2], s[n2 + 1][3]));
#pragma unroll
            for (int ndp = 0; ndp < 4; ndp++) {
                const int nd = ndp * 2;
                const uint32_t off = bob + (uint32_t)((ks2 * 16 * KPAD + nd * 8) * 2);
                uint32_t bh0, bh1, bh2, bh3;
                ldsm_x4_t(bh0, bh1, bh2, bh3, aV0 + off);
                mma16816(o[nd],     pah, bh0, bh1);
                mma16816(o[nd + 1], pah, bh2, bh3);
            }
        }
        __syncthreads();
    }

    // ---- epilogue ----
    const float inv0 = 1.f / l0;
    const float inv1 = 1.f / l1;
    float* ob = out + (size_t)b * SEQ * NSTATE + (size_t)h * DHEAD;
#pragma unroll
    for (int nd = 0; nd < 8; nd++) {
        const int dcol = nd * 8 + qr * 2;
        float2 v0; v0.x = o[nd][0] * inv0; v0.y = o[nd][1] * inv0;
        float2 v1; v1.x = o[nd][2] * inv1; v1.y = o[nd][3] * inv1;
        *reinterpret_cast<float2*>(ob + (size_t)row0 * NSTATE + dcol) = v0;
        *reinterpret_cast<float2*>(ob + (size_t)(row0 + 8) * NSTATE + dcol) = v1;
    }
}

extern "C" void kernel_launch(void* const* d_in, const int* in_sizes, int n_in,
                              void* d_out, int out_size) {
    const float* x = (const float*)d_in[0];
    float* out = (float*)d_out;
    conv_kernel<<<BATCH * SEQ, 256>>>(x);
    dim3 grid(SEQ / BM, NHEAD, BATCH);
    fa_kernel<<<grid, NTHREADS>>>(x, out);
}